// round 3
// baseline (speedup 1.0000x reference)
#include <cuda_runtime.h>

// ---------------------------------------------------------------------------
// TransformerLayer: B=4, S=2048, D=512, H=8, d_k=64, FF=2048, fp32, dense mask
//
// Pipeline:
//   Q/K/V = x@W + b   (SGEMM x3)
//   ctx   = flash_attention(Q, K, V)        (online softmax, scale 1/8)
//   a     = ctx@Wo + bo                     (SGEMM)
//   h     = LN(x + a)                       (fused add+LN)
//   f     = relu(h@W1 + b1)                 (SGEMM + ReLU)
//   f2    = f@W2 + b2                       (SGEMM)
//   out   = LN(h + f2)                      (fused add+LN)
// ---------------------------------------------------------------------------

#define MROWS   8192      // B*S
#define DMODEL  512
#define DFF     2048
#define SEQ     2048
#define NH      8
#define DH      64
#define BQ      64
#define BK      64
#define NEG_BIG (-1e30f)

// scratch (static __device__ arrays: the sanctioned no-alloc workaround)
__device__ float g_q  [MROWS * DMODEL];
__device__ float g_k  [MROWS * DMODEL];
__device__ float g_v  [MROWS * DMODEL];
__device__ float g_ctx[MROWS * DMODEL];
__device__ float g_h  [MROWS * DMODEL];
__device__ float g_t  [MROWS * DMODEL];
__device__ float g_ff [MROWS * DFF];

// ---------------------------------------------------------------------------
// SGEMM: C[M,N] = A[M,K] @ B[K,N] + bias[N]   (optional ReLU)
// 128x128 tile, BK=8, 256 threads, 8x8 per-thread register tile.
// ---------------------------------------------------------------------------
template <bool RELU>
__global__ __launch_bounds__(256)
void sgemm_bias(const float* __restrict__ A, const float* __restrict__ B,
                const float* __restrict__ bias, float* __restrict__ C,
                int M, int N, int K)
{
    __shared__ float As[8][128];
    __shared__ float Bs[8][128];

    const int tid  = threadIdx.x;
    const int tx   = tid & 15;
    const int ty   = tid >> 4;
    const int arow = tid >> 1;
    const int acol = (tid & 1) << 2;
    const int brow = tid >> 5;
    const int bcol = (tid & 31) << 2;

    const float* Ap = A + ((size_t)blockIdx.y * 128 + arow) * K + acol;
    const float* Bp = B + (size_t)brow * N + (size_t)blockIdx.x * 128 + bcol;

    float acc[8][8];
#pragma unroll
    for (int i = 0; i < 8; i++)
#pragma unroll
        for (int j = 0; j < 8; j++) acc[i][j] = 0.f;

    for (int k0 = 0; k0 < K; k0 += 8) {
        float4 av = *(const float4*)(Ap + k0);
        float4 bv = *(const float4*)(Bp + (size_t)k0 * N);
        As[acol + 0][arow] = av.x;
        As[acol + 1][arow] = av.y;
        As[acol + 2][arow] = av.z;
        As[acol + 3][arow] = av.w;
        *(float4*)&Bs[brow][bcol] = bv;
        __syncthreads();

#pragma unroll
        for (int kk = 0; kk < 8; kk++) {
            float af[8], bf[8];
            *(float4*)(af)     = *(const float4*)&As[kk][ty * 8];
            *(float4*)(af + 4) = *(const float4*)&As[kk][ty * 8 + 4];
            *(float4*)(bf)     = *(const float4*)&Bs[kk][tx * 8];
            *(float4*)(bf + 4) = *(const float4*)&Bs[kk][tx * 8 + 4];
#pragma unroll
            for (int i = 0; i < 8; i++)
#pragma unroll
                for (int j = 0; j < 8; j++)
                    acc[i][j] = fmaf(af[i], bf[j], acc[i][j]);
        }
        __syncthreads();
    }

    const int row0 = blockIdx.y * 128 + ty * 8;
    const int col0 = blockIdx.x * 128 + tx * 8;
    float bb[8];
#pragma unroll
    for (int j = 0; j < 8; j++) bb[j] = bias[col0 + j];

#pragma unroll
    for (int i = 0; i < 8; i++) {
        float o[8];
#pragma unroll
        for (int j = 0; j < 8; j++) {
            float v = acc[i][j] + bb[j];
            if (RELU) v = fmaxf(v, 0.f);
            o[j] = v;
        }
        float* cp = C + (size_t)(row0 + i) * N + col0;
        *(float4*)(cp)     = *(float4*)(o);
        *(float4*)(cp + 4) = *(float4*)(o + 4);
    }
}

// ---------------------------------------------------------------------------
// Flash attention, fp32. Grid: (S/BQ, H, B). 256 threads.
// Q/K held transposed in smem (padded stride BQ+4) for conflict-free frags.
// ---------------------------------------------------------------------------
__global__ __launch_bounds__(256)
void flash_attn(const float* __restrict__ Qg, const float* __restrict__ Kg,
                const float* __restrict__ Vg, float* __restrict__ Og)
{
    extern __shared__ float sm[];
    float (*Qst)[BQ + 4] = (float (*)[BQ + 4])sm;                          // [DH][BQ+4]
    float (*Kst)[BK + 4] = (float (*)[BK + 4])(sm + DH * (BQ + 4));        // [DH][BK+4]
    float (*Vs )[DH]     = (float (*)[DH])    (sm + 2 * DH * (BQ + 4));    // [BK][DH]
    float (*Ss )[BK + 4] = (float (*)[BK + 4])(sm + 2 * DH * (BQ + 4) + BK * DH);
    float* m_s  = sm + 2 * DH * (BQ + 4) + BK * DH + BQ * (BK + 4);
    float* l_s  = m_s  + BQ;
    float* sc_s = l_s  + BQ;
    float* pm   = sc_s + BQ;        // [BQ][4]
    float* ps   = pm   + BQ * 4;    // [BQ][4]

    const int tid = threadIdx.x;
    const int tx  = tid & 15;
    const int ty  = tid >> 4;
    const int h   = blockIdx.y;
    const int b   = blockIdx.z;
    const int q0  = blockIdx.x * BQ;

    // load Q tile, transposed into Qst[d][r]
    {
        const int r  = tid >> 2;
        const int d0 = (tid & 3) * 16;
        const float* qp = Qg + (size_t)(b * SEQ + q0 + r) * DMODEL + h * DH + d0;
#pragma unroll
        for (int c4 = 0; c4 < 4; c4++) {
            float4 v = *(const float4*)(qp + c4 * 4);
            Qst[d0 + c4 * 4 + 0][r] = v.x;
            Qst[d0 + c4 * 4 + 1][r] = v.y;
            Qst[d0 + c4 * 4 + 2][r] = v.z;
            Qst[d0 + c4 * 4 + 3][r] = v.w;
        }
    }
    if (tid < BQ) { m_s[tid] = NEG_BIG; l_s[tid] = 0.f; }

    float oacc[4][4];
#pragma unroll
    for (int i = 0; i < 4; i++)
#pragma unroll
        for (int j = 0; j < 4; j++) oacc[i][j] = 0.f;

    const int rr = tid >> 2;
    const int qq = tid & 3;

    for (int kt = 0; kt < SEQ / BK; kt++) {
        __syncthreads();   // protects Kst/Vs/Ss reuse vs previous iteration readers

        // load K tile transposed
        {
            const int r  = tid >> 2;
            const int d0 = (tid & 3) * 16;
            const float* kp = Kg + (size_t)(b * SEQ + kt * BK + r) * DMODEL + h * DH + d0;
#pragma unroll
            for (int c4 = 0; c4 < 4; c4++) {
                float4 v = *(const float4*)(kp + c4 * 4);
                Kst[d0 + c4 * 4 + 0][r] = v.x;
                Kst[d0 + c4 * 4 + 1][r] = v.y;
                Kst[d0 + c4 * 4 + 2][r] = v.z;
                Kst[d0 + c4 * 4 + 3][r] = v.w;
            }
        }
        // load V tile (natural layout)
        {
            const float* vp = Vg + (size_t)(b * SEQ + kt * BK) * DMODEL + h * DH;
#pragma unroll
            for (int i = 0; i < 4; i++) {
                int e   = tid + i * 256;       // float4 index (1024 total)
                int key = e >> 4;
                int dd  = (e & 15) << 2;
                *(float4*)&Vs[key][dd] = *(const float4*)(vp + (size_t)key * DMODEL + dd);
            }
        }
        __syncthreads();

        // S = Q @ K^T  (4x4 per thread)
        float s[4][4];
#pragma unroll
        for (int i = 0; i < 4; i++)
#pragma unroll
            for (int j = 0; j < 4; j++) s[i][j] = 0.f;

#pragma unroll 8
        for (int k = 0; k < DH; k++) {
            float4 aq = *(const float4*)&Qst[k][ty * 4];
            float4 bk = *(const float4*)&Kst[k][tx * 4];
            float af[4] = {aq.x, aq.y, aq.z, aq.w};
            float bf[4] = {bk.x, bk.y, bk.z, bk.w};
#pragma unroll
            for (int i = 0; i < 4; i++)
#pragma unroll
                for (int j = 0; j < 4; j++)
                    s[i][j] = fmaf(af[i], bf[j], s[i][j]);
        }
#pragma unroll
        for (int i = 0; i < 4; i++)
#pragma unroll
            for (int j = 0; j < 4; j++)
                Ss[ty * 4 + i][tx * 4 + j] = s[i][j] * 0.125f;   // 1/sqrt(64)
        __syncthreads();

        // per-row partial max (each thread: one row quarter)
        {
            float mx = NEG_BIG;
#pragma unroll
            for (int c = 0; c < 16; c++) mx = fmaxf(mx, Ss[rr][qq * 16 + c]);
            pm[rr * 4 + qq] = mx;
        }
        __syncthreads();

        if (tid < BQ) {
            float mc = fmaxf(fmaxf(pm[tid * 4], pm[tid * 4 + 1]),
                             fmaxf(pm[tid * 4 + 2], pm[tid * 4 + 3]));
            float mo = m_s[tid];
            float mn = fmaxf(mo, mc);
            sc_s[tid] = __expf(mo - mn);      // exp(-1e30-x) underflows to 0 on first tile
            m_s[tid]  = mn;
        }
        __syncthreads();

        // exponentiate in place + partial sums
        {
            float mrow = m_s[rr];
            float sum  = 0.f;
#pragma unroll
            for (int c = 0; c < 16; c++) {
                float e = __expf(Ss[rr][qq * 16 + c] - mrow);
                Ss[rr][qq * 16 + c] = e;
                sum += e;
            }
            ps[rr * 4 + qq] = sum;
        }
        __syncthreads();

        if (tid < BQ)
            l_s[tid] = l_s[tid] * sc_s[tid]
                     + ps[tid * 4] + ps[tid * 4 + 1] + ps[tid * 4 + 2] + ps[tid * 4 + 3];

        // rescale accumulators, then O += P @ V
        float scl[4];
#pragma unroll
        for (int i = 0; i < 4; i++) scl[i] = sc_s[ty * 4 + i];
#pragma unroll
        for (int i = 0; i < 4; i++)
#pragma unroll
            for (int j = 0; j < 4; j++) oacc[i][j] *= scl[i];

#pragma unroll 8
        for (int kk = 0; kk < BK; kk++) {
            float a0 = Ss[ty * 4 + 0][kk];
            float a1 = Ss[ty * 4 + 1][kk];
            float a2 = Ss[ty * 4 + 2][kk];
            float a3 = Ss[ty * 4 + 3][kk];
            float4 v4 = *(const float4*)&Vs[kk][tx * 4];
            float bf[4] = {v4.x, v4.y, v4.z, v4.w};
#pragma unroll
            for (int j = 0; j < 4; j++) {
                oacc[0][j] = fmaf(a0, bf[j], oacc[0][j]);
                oacc[1][j] = fmaf(a1, bf[j], oacc[1][j]);
                oacc[2][j] = fmaf(a2, bf[j], oacc[2][j]);
                oacc[3][j] = fmaf(a3, bf[j], oacc[3][j]);
            }
        }
    }
    __syncthreads();

    // normalize and store ctx in [B,S,H*DH] layout
#pragma unroll
    for (int i = 0; i < 4; i++) {
        int r = ty * 4 + i;
        float inv = 1.f / l_s[r];
        float4 o;
        o.x = oacc[i][0] * inv;
        o.y = oacc[i][1] * inv;
        o.z = oacc[i][2] * inv;
        o.w = oacc[i][3] * inv;
        *(float4*)&Og[(size_t)(b * SEQ + q0 + r) * DMODEL + h * DH + tx * 4] = o;
    }
}

// ---------------------------------------------------------------------------
// Fused residual-add + LayerNorm over D=512. One block (128 thr) per row.
// ---------------------------------------------------------------------------
__global__ __launch_bounds__(128)
void add_ln(const float* __restrict__ A, const float* __restrict__ Bm,
            const float* __restrict__ gw, const float* __restrict__ bw,
            float* __restrict__ out)
{
    const int row = blockIdx.x;
    const int t   = threadIdx.x;

    float4 a = ((const float4*)(A  + (size_t)row * DMODEL))[t];
    float4 b = ((const float4*)(Bm + (size_t)row * DMODEL))[t];
    float v[4] = {a.x + b.x, a.y + b.y, a.z + b.z, a.w + b.w};

    float s  = v[0] + v[1] + v[2] + v[3];
    float ss = v[0] * v[0] + v[1] * v[1] + v[2] * v[2] + v[3] * v[3];
#pragma unroll
    for (int o = 16; o > 0; o >>= 1) {
        s  += __shfl_xor_sync(0xffffffffu, s,  o);
        ss += __shfl_xor_sync(0xffffffffu, ss, o);
    }

    __shared__ float ws[4], wss[4];
    __shared__ float mu_sh, rs_sh;
    const int warp = t >> 5, lane = t & 31;
    if (lane == 0) { ws[warp] = s; wss[warp] = ss; }
    __syncthreads();
    if (t == 0) {
        float S  = ws[0]  + ws[1]  + ws[2]  + ws[3];
        float SS = wss[0] + wss[1] + wss[2] + wss[3];
        float mu  = S * (1.f / DMODEL);
        float var = SS * (1.f / DMODEL) - mu * mu;
        mu_sh = mu;
        rs_sh = rsqrtf(var + 1e-5f);
    }
    __syncthreads();

    const float mu = mu_sh, rs = rs_sh;
    float4 g4 = ((const float4*)gw)[t];
    float4 b4 = ((const float4*)bw)[t];
    float4 o;
    o.x = (v[0] - mu) * rs * g4.x + b4.x;
    o.y = (v[1] - mu) * rs * g4.y + b4.y;
    o.z = (v[2] - mu) * rs * g4.z + b4.z;
    o.w = (v[3] - mu) * rs * g4.w + b4.w;
    ((float4*)(out + (size_t)row * DMODEL))[t] = o;
}

// ---------------------------------------------------------------------------
extern "C" void kernel_launch(void* const* d_in, const int* in_sizes, int n_in,
                              void* d_out, int out_size)
{
    (void)in_sizes; (void)n_in; (void)out_size;

    const float* x   = (const float*)d_in[0];
    // d_in[1] = mask: all ones in this problem -> dense attention, ignored
    const float* Wq  = (const float*)d_in[2];
    const float* bq  = (const float*)d_in[3];
    const float* Wk  = (const float*)d_in[4];
    const float* bk  = (const float*)d_in[5];
    const float* Wv  = (const float*)d_in[6];
    const float* bv  = (const float*)d_in[7];
    const float* Wo  = (const float*)d_in[8];
    const float* bo  = (const float*)d_in[9];
    const float* W1  = (const float*)d_in[10];
    const float* b1  = (const float*)d_in[11];
    const float* W2  = (const float*)d_in[12];
    const float* b2  = (const float*)d_in[13];
    const float* g1  = (const float*)d_in[14];
    const float* be1 = (const float*)d_in[15];
    const float* g2  = (const float*)d_in[16];
    const float* be2 = (const float*)d_in[17];
    float* out = (float*)d_out;

    float *q, *k, *v, *ctx, *h, *t, *ff;
    cudaGetSymbolAddress((void**)&q,   g_q);
    cudaGetSymbolAddress((void**)&k,   g_k);
    cudaGetSymbolAddress((void**)&v,   g_v);
    cudaGetSymbolAddress((void**)&ctx, g_ctx);
    cudaGetSymbolAddress((void**)&h,   g_h);
    cudaGetSymbolAddress((void**)&t,   g_t);
    cudaGetSymbolAddress((void**)&ff,  g_ff);

    const dim3 blk(256);
    const dim3 g512(DMODEL / 128, MROWS / 128);
    const dim3 gff (DFF    / 128, MROWS / 128);

    // QKV projections
    sgemm_bias<false><<<g512, blk>>>(x, Wq, bq, q, MROWS, DMODEL, DMODEL);
    sgemm_bias<false><<<g512, blk>>>(x, Wk, bk, k, MROWS, DMODEL, DMODEL);
    sgemm_bias<false><<<g512, blk>>>(x, Wv, bv, v, MROWS, DMODEL, DMODEL);

    // flash attention
    const int FA_SMEM = (2 * DH * (BQ + 4) + BK * DH + BQ * (BK + 4) + 11 * BQ)
                        * (int)sizeof(float);   // 71424 B
    cudaFuncSetAttribute(flash_attn, cudaFuncAttributeMaxDynamicSharedMemorySize, FA_SMEM);
    flash_attn<<<dim3(SEQ / BQ, NH, 4), 256, FA_SMEM>>>(q, k, v, ctx);

    // output projection + LN1
    sgemm_bias<false><<<g512, blk>>>(ctx, Wo, bo, t, MROWS, DMODEL, DMODEL);
    add_ln<<<MROWS, 128>>>(x, t, g1, be1, h);

    // FFN + LN2
    sgemm_bias<true ><<<gff,  blk>>>(h,  W1, b1, ff, MROWS, DFF,    DMODEL);
    sgemm_bias<false><<<g512, blk>>>(ff, W2, b2, t,  MROWS, DMODEL, DFF);
    add_ln<<<MROWS, 128>>>(h, t, g2, be2, out);
}